// round 12
// baseline (speedup 1.0000x reference)
#include <cuda_runtime.h>

// 4-level 2D Haar DWT, fully fused. Tile = 64x128 input (WIDE) per 256-thread
// block: per-warp DRAM touches are 512B-contiguous loads and 256B-contiguous
// subband stores (2x the burst length of the 64x64 version) to raise HBM
// stream efficiency. Level 0 fully in registers (8x LDG.128 up front),
// cascade via SMEM. No cache hints (measured regressions).
// Grid: (4, 8, 192) = 6144 blocks.
//
// Input : x (64, 3, 512, 512) f32 -> 192 images of 512x512
// Output: concat of levels l=0..3, each (192, 4, S, S), S = 256 >> l
//   subband order: 0=cA, 1=cH, 2=cV, 3=cD

#define NIMG 192
#define HW   512

#define OFF0 0ull
#define OFF1 (OFF0 + (unsigned long long)NIMG * 4ull * 256ull * 256ull)
#define OFF2 (OFF1 + (unsigned long long)NIMG * 4ull * 128ull * 128ull)
#define OFF3 (OFF2 + (unsigned long long)NIMG * 4ull *  64ull *  64ull)

#define HAAR(a, b, c, d, cA, cH, cV, cD)                    \
    do {                                                    \
        float _hs0 = (a) + (b), _hd0 = (a) - (b);           \
        float _hs1 = (c) + (d), _hd1 = (c) - (d);           \
        (cA) = (_hs0 + _hs1) * 0.5f;                        \
        (cH) = (_hs0 - _hs1) * 0.5f;                        \
        (cV) = (_hd0 + _hd1) * 0.5f;                        \
        (cD) = (_hd0 - _hd1) * 0.5f;                        \
    } while (0)

// 4 adjacent quads from two row-pair float4s -> 4 subband float4s
#define HAAR4(r0a, r0b, r1a, r1b, cA4, cH4, cV4, cD4)                                 \
    do {                                                                              \
        HAAR((r0a).x, (r0a).y, (r1a).x, (r1a).y, (cA4).x, (cH4).x, (cV4).x, (cD4).x); \
        HAAR((r0a).z, (r0a).w, (r1a).z, (r1a).w, (cA4).y, (cH4).y, (cV4).y, (cD4).y); \
        HAAR((r0b).x, (r0b).y, (r1b).x, (r1b).y, (cA4).z, (cH4).z, (cV4).z, (cD4).z); \
        HAAR((r0b).z, (r0b).w, (r1b).z, (r1b).w, (cA4).w, (cH4).w, (cV4).w, (cD4).w); \
    } while (0)

__global__ __launch_bounds__(256) void fwt_kernel(const float* __restrict__ x,
                                                  float* __restrict__ out) {
    const int img = blockIdx.z;
    const int ty  = blockIdx.y;   // 0..7  (64-row slabs)
    const int tx  = blockIdx.x;   // 0..3  (128-col slabs)
    const int tid = threadIdx.x;

    __shared__ float sB[32][65];  // level-0 cA (32x64)
    __shared__ float sC[16][33];  // level-1 cA (16x32)
    __shared__ float sD[8][17];   // level-2 cA (8x16)

    // ---- level 0: 64x128 input -> 32x64 quads, S=256 ----
    {
        const int qi  = tid >> 3;   // 0..31 quad row
        const int qjg = tid & 7;    // 8-quad col group -> input cols qjg*16..+15

        const float* src = x + ((size_t)img * HW + (size_t)ty * 64 + 2 * qi) * HW
                             + (size_t)tx * 128 + qjg * 16;
        // all 8 loads issued before compute; warp covers 512B contiguous/row
        const float4 r0a = *reinterpret_cast<const float4*>(src);
        const float4 r0b = *reinterpret_cast<const float4*>(src + 4);
        const float4 r0c = *reinterpret_cast<const float4*>(src + 8);
        const float4 r0d = *reinterpret_cast<const float4*>(src + 12);
        const float4 r1a = *reinterpret_cast<const float4*>(src + HW);
        const float4 r1b = *reinterpret_cast<const float4*>(src + HW + 4);
        const float4 r1c = *reinterpret_cast<const float4*>(src + HW + 8);
        const float4 r1d = *reinterpret_cast<const float4*>(src + HW + 12);

        float4 cAa, cHa, cVa, cDa, cAb, cHb, cVb, cDb;
        HAAR4(r0a, r0b, r1a, r1b, cAa, cHa, cVa, cDa);
        HAAR4(r0c, r0d, r1c, r1d, cAb, cHb, cVb, cDb);

        const int S = 256;
        float* base = out + OFF0 + (size_t)img * 4ull * S * S;
        const int gi = ty * 32 + qi, gj = tx * 64 + qjg * 8;
        const size_t o = (size_t)gi * S + gj;
        *reinterpret_cast<float4*>(base + o)                     = cAa;
        *reinterpret_cast<float4*>(base + o + 4)                 = cAb;
        *reinterpret_cast<float4*>(base + (size_t)S * S + o)     = cHa;
        *reinterpret_cast<float4*>(base + (size_t)S * S + o + 4) = cHb;
        *reinterpret_cast<float4*>(base + 2ull * S * S + o)      = cVa;
        *reinterpret_cast<float4*>(base + 2ull * S * S + o + 4)  = cVb;
        *reinterpret_cast<float4*>(base + 3ull * S * S + o)      = cDa;
        *reinterpret_cast<float4*>(base + 3ull * S * S + o + 4)  = cDb;

        float* sbr = &sB[qi][qjg * 8];
        sbr[0] = cAa.x; sbr[1] = cAa.y; sbr[2] = cAa.z; sbr[3] = cAa.w;
        sbr[4] = cAb.x; sbr[5] = cAb.y; sbr[6] = cAb.z; sbr[7] = cAb.w;
    }
    __syncthreads();

    // ---- level 1: 32x64 -> 16x32 quads, S=128 (256 threads x 2 quads) ----
    {
        const int qi = tid >> 4;        // 0..15
        const int qj = (tid & 15) * 2;  // 0,2,..,30 (2 adjacent quads)

        float2 cA2, cH2, cV2, cD2;
        {
            const int r0 = 2 * qi, r1 = 2 * qi + 1, c0 = 2 * qj;
            HAAR(sB[r0][c0 + 0], sB[r0][c0 + 1], sB[r1][c0 + 0], sB[r1][c0 + 1],
                 cA2.x, cH2.x, cV2.x, cD2.x);
            HAAR(sB[r0][c0 + 2], sB[r0][c0 + 3], sB[r1][c0 + 2], sB[r1][c0 + 3],
                 cA2.y, cH2.y, cV2.y, cD2.y);
        }

        const int S = 128;
        float* base = out + OFF1 + (size_t)img * 4ull * S * S;
        const int gi = ty * 16 + qi, gj = tx * 32 + qj;
        const size_t o = (size_t)gi * S + gj;
        *reinterpret_cast<float2*>(base + o)                 = cA2;
        *reinterpret_cast<float2*>(base + (size_t)S * S + o) = cH2;
        *reinterpret_cast<float2*>(base + 2ull * S * S + o)  = cV2;
        *reinterpret_cast<float2*>(base + 3ull * S * S + o)  = cD2;

        sC[qi][qj]     = cA2.x;
        sC[qi][qj + 1] = cA2.y;
    }
    __syncthreads();

    // ---- level 2: 16x32 -> 8x16 quads, S=64 (128 threads x 1 quad) ----
    if (tid < 128) {
        const int qi = tid >> 4;    // 0..7
        const int qj = tid & 15;    // 0..15

        float cAv, cHv, cVv, cDv;
        HAAR(sC[2 * qi][2 * qj], sC[2 * qi][2 * qj + 1],
             sC[2 * qi + 1][2 * qj], sC[2 * qi + 1][2 * qj + 1],
             cAv, cHv, cVv, cDv);

        const int S = 64;
        float* base = out + OFF2 + (size_t)img * 4ull * S * S;
        const int gi = ty * 8 + qi, gj = tx * 16 + qj;
        const size_t o = (size_t)gi * S + gj;
        base[o]                 = cAv;
        base[(size_t)S * S + o] = cHv;
        base[2ull * S * S + o]  = cVv;
        base[3ull * S * S + o]  = cDv;

        sD[qi][qj] = cAv;
    }
    __syncthreads();

    // ---- level 3: 8x16 -> 4x8 quads, S=32 (32 threads x 1 quad) ----
    if (tid < 32) {
        const int qi = tid >> 3;    // 0..3
        const int qj = tid & 7;     // 0..7

        float cAv, cHv, cVv, cDv;
        HAAR(sD[2 * qi][2 * qj], sD[2 * qi][2 * qj + 1],
             sD[2 * qi + 1][2 * qj], sD[2 * qi + 1][2 * qj + 1],
             cAv, cHv, cVv, cDv);

        const int S = 32;
        float* base = out + OFF3 + (size_t)img * 4ull * S * S;
        const int gi = ty * 4 + qi, gj = tx * 8 + qj;
        const size_t o = (size_t)gi * S + gj;
        base[o]                 = cAv;
        base[(size_t)S * S + o] = cHv;
        base[2ull * S * S + o]  = cVv;
        base[3ull * S * S + o]  = cDv;
    }
}

extern "C" void kernel_launch(void* const* d_in, const int* in_sizes, int n_in,
                              void* d_out, int out_size) {
    const float* x = (const float*)d_in[0];
    float* out     = (float*)d_out;
    dim3 grid(4, 8, NIMG);
    fwt_kernel<<<grid, 256>>>(x, out);
}

// round 13
// speedup vs baseline: 1.1943x; 1.1943x over previous
#include <cuda_runtime.h>

// 4-level 2D Haar DWT, fully fused. R2 structure with PERFECT per-instruction
// load coalescing at level 0: each warp-wide LDG.128 covers two fully-dense
// 256B row segments (lanes 0-15 -> row r, lanes 16-31 -> row r'), 100% sector
// utilization (R2 was 50%/instruction). Each thread owns one float4 (2 quads)
// on two quad-row groups; subband stores are float2 (128B dense per half-warp).
// Levels 1-3 verbatim from R2. No cache hints (measured regressions).
// Grid: (8, 8, 192), 256 threads.
//
// Input : x (64, 3, 512, 512) f32 -> 192 images of 512x512
// Output: concat of levels l=0..3, each (192, 4, S, S), S = 256 >> l
//   subband order: 0=cA, 1=cH, 2=cV, 3=cD

#define NIMG 192
#define HW   512

#define OFF0 0ull
#define OFF1 (OFF0 + (unsigned long long)NIMG * 4ull * 256ull * 256ull)
#define OFF2 (OFF1 + (unsigned long long)NIMG * 4ull * 128ull * 128ull)
#define OFF3 (OFF2 + (unsigned long long)NIMG * 4ull *  64ull *  64ull)

#define HAAR(a, b, c, d, cA, cH, cV, cD)                    \
    do {                                                    \
        float _hs0 = (a) + (b), _hd0 = (a) - (b);           \
        float _hs1 = (c) + (d), _hd1 = (c) - (d);           \
        (cA) = (_hs0 + _hs1) * 0.5f;                        \
        (cH) = (_hs0 - _hs1) * 0.5f;                        \
        (cV) = (_hd0 + _hd1) * 0.5f;                        \
        (cD) = (_hd0 - _hd1) * 0.5f;                        \
    } while (0)

__global__ __launch_bounds__(256) void fwt_kernel(const float* __restrict__ x,
                                                  float* __restrict__ out) {
    const int img = blockIdx.z;
    const int ty  = blockIdx.y;
    const int tx  = blockIdx.x;
    const int tid = threadIdx.x;

    __shared__ float sB[32][33];  // level-0 cA
    __shared__ float sC[16][17];  // level-1 cA
    __shared__ float sD[8][9];    // level-2 cA

    // ---- level 0: 64x64 tile -> 32x32 quads, S=256 ----
    // lane layout: w=warp(0..7), half=(lane>>4), c=(lane&15)
    //   quad rows qr0 = 2w+half (0..15) and qr1 = qr0+16
    //   thread covers cols c*4..c*4+3 (one float4 = 2 quads) per quad row.
    // Per LDG.128: lanes 0-15 = 256B dense @ row 4w(+1), lanes 16-31 = 256B
    // dense @ row 4w+2(+3). All sectors full.
    {
        const int w    = tid >> 5;
        const int l    = tid & 31;
        const int half = l >> 4;
        const int c    = l & 15;
        const int qr0  = 2 * w + half;   // 0..15
        const int qr1  = qr0 + 16;       // 16..31

        const float* srcb = x + ((size_t)img * HW + (size_t)ty * 64) * HW
                              + (size_t)tx * 64 + c * 4;
        const float* s0 = srcb + (size_t)(2 * qr0) * HW;
        const float* s1 = srcb + (size_t)(2 * qr1) * HW;

        // all 4 loads issued before compute
        const float4 a0 = *reinterpret_cast<const float4*>(s0);
        const float4 b0 = *reinterpret_cast<const float4*>(s0 + HW);
        const float4 a1 = *reinterpret_cast<const float4*>(s1);
        const float4 b1 = *reinterpret_cast<const float4*>(s1 + HW);

        const int S = 256;
        float* base = out + OFF0 + (size_t)img * 4ull * S * S;
        const int gj = tx * 32 + c * 2;

        // quad-row group 0
        {
            float2 cA2, cH2, cV2, cD2;
            HAAR(a0.x, a0.y, b0.x, b0.y, cA2.x, cH2.x, cV2.x, cD2.x);
            HAAR(a0.z, a0.w, b0.z, b0.w, cA2.y, cH2.y, cV2.y, cD2.y);
            const int gi = ty * 32 + qr0;
            const size_t o = (size_t)gi * S + gj;
            *reinterpret_cast<float2*>(base + o)                 = cA2;
            *reinterpret_cast<float2*>(base + (size_t)S * S + o) = cH2;
            *reinterpret_cast<float2*>(base + 2ull * S * S + o)  = cV2;
            *reinterpret_cast<float2*>(base + 3ull * S * S + o)  = cD2;
            sB[qr0][c * 2]     = cA2.x;
            sB[qr0][c * 2 + 1] = cA2.y;
        }
        // quad-row group 1
        {
            float2 cA2, cH2, cV2, cD2;
            HAAR(a1.x, a1.y, b1.x, b1.y, cA2.x, cH2.x, cV2.x, cD2.x);
            HAAR(a1.z, a1.w, b1.z, b1.w, cA2.y, cH2.y, cV2.y, cD2.y);
            const int gi = ty * 32 + qr1;
            const size_t o = (size_t)gi * S + gj;
            *reinterpret_cast<float2*>(base + o)                 = cA2;
            *reinterpret_cast<float2*>(base + (size_t)S * S + o) = cH2;
            *reinterpret_cast<float2*>(base + 2ull * S * S + o)  = cV2;
            *reinterpret_cast<float2*>(base + 3ull * S * S + o)  = cD2;
            sB[qr1][c * 2]     = cA2.x;
            sB[qr1][c * 2 + 1] = cA2.y;
        }
    }
    __syncthreads();

    // ---- level 1: 32x32 -> 16x16, S=128 (64 threads x 4 quads) ----
    if (tid < 64) {
        const int qi  = tid >> 2;   // 0..15
        const int qjg = tid & 3;    // cols qjg*8..+7 of sB

        float4 cA4, cH4, cV4, cD4;
        {
            const int r0 = 2 * qi, r1 = 2 * qi + 1, c0 = qjg * 8;
            HAAR(sB[r0][c0 + 0], sB[r0][c0 + 1], sB[r1][c0 + 0], sB[r1][c0 + 1],
                 cA4.x, cH4.x, cV4.x, cD4.x);
            HAAR(sB[r0][c0 + 2], sB[r0][c0 + 3], sB[r1][c0 + 2], sB[r1][c0 + 3],
                 cA4.y, cH4.y, cV4.y, cD4.y);
            HAAR(sB[r0][c0 + 4], sB[r0][c0 + 5], sB[r1][c0 + 4], sB[r1][c0 + 5],
                 cA4.z, cH4.z, cV4.z, cD4.z);
            HAAR(sB[r0][c0 + 6], sB[r0][c0 + 7], sB[r1][c0 + 6], sB[r1][c0 + 7],
                 cA4.w, cH4.w, cV4.w, cD4.w);
        }

        const int S = 128;
        float* base = out + OFF1 + (size_t)img * 4ull * S * S;
        const int gi = ty * 16 + qi, gj = tx * 16 + qjg * 4;
        const size_t o = (size_t)gi * S + gj;
        *reinterpret_cast<float4*>(base + o)                 = cA4;
        *reinterpret_cast<float4*>(base + (size_t)S * S + o) = cH4;
        *reinterpret_cast<float4*>(base + 2ull * S * S + o)  = cV4;
        *reinterpret_cast<float4*>(base + 3ull * S * S + o)  = cD4;

        sC[qi][qjg * 4 + 0] = cA4.x;
        sC[qi][qjg * 4 + 1] = cA4.y;
        sC[qi][qjg * 4 + 2] = cA4.z;
        sC[qi][qjg * 4 + 3] = cA4.w;
    }
    __syncthreads();

    // ---- level 2: 16x16 -> 8x8, S=64 (16 threads x 4 quads) ----
    if (tid < 16) {
        const int qi  = tid >> 1;   // 0..7
        const int qjg = tid & 1;    // cols qjg*8..+7 of sC

        float4 cA4, cH4, cV4, cD4;
        {
            const int r0 = 2 * qi, r1 = 2 * qi + 1, c0 = qjg * 8;
            HAAR(sC[r0][c0 + 0], sC[r0][c0 + 1], sC[r1][c0 + 0], sC[r1][c0 + 1],
                 cA4.x, cH4.x, cV4.x, cD4.x);
            HAAR(sC[r0][c0 + 2], sC[r0][c0 + 3], sC[r1][c0 + 2], sC[r1][c0 + 3],
                 cA4.y, cH4.y, cV4.y, cD4.y);
            HAAR(sC[r0][c0 + 4], sC[r0][c0 + 5], sC[r1][c0 + 4], sC[r1][c0 + 5],
                 cA4.z, cH4.z, cV4.z, cD4.z);
            HAAR(sC[r0][c0 + 6], sC[r0][c0 + 7], sC[r1][c0 + 6], sC[r1][c0 + 7],
                 cA4.w, cH4.w, cV4.w, cD4.w);
        }

        const int S = 64;
        float* base = out + OFF2 + (size_t)img * 4ull * S * S;
        const int gi = ty * 8 + qi, gj = tx * 8 + qjg * 4;
        const size_t o = (size_t)gi * S + gj;
        *reinterpret_cast<float4*>(base + o)                 = cA4;
        *reinterpret_cast<float4*>(base + (size_t)S * S + o) = cH4;
        *reinterpret_cast<float4*>(base + 2ull * S * S + o)  = cV4;
        *reinterpret_cast<float4*>(base + 3ull * S * S + o)  = cD4;

        sD[qi][qjg * 4 + 0] = cA4.x;
        sD[qi][qjg * 4 + 1] = cA4.y;
        sD[qi][qjg * 4 + 2] = cA4.z;
        sD[qi][qjg * 4 + 3] = cA4.w;
    }
    __syncthreads();

    // ---- level 3: 8x8 -> 4x4, S=32 (4 threads x 4 quads) ----
    if (tid < 4) {
        const int qi = tid;  // 0..3, full 4-quad row

        float4 cA4, cH4, cV4, cD4;
        {
            const int r0 = 2 * qi, r1 = 2 * qi + 1;
            HAAR(sD[r0][0], sD[r0][1], sD[r1][0], sD[r1][1], cA4.x, cH4.x, cV4.x, cD4.x);
            HAAR(sD[r0][2], sD[r0][3], sD[r1][2], sD[r1][3], cA4.y, cH4.y, cV4.y, cD4.y);
            HAAR(sD[r0][4], sD[r0][5], sD[r1][4], sD[r1][5], cA4.z, cH4.z, cV4.z, cD4.z);
            HAAR(sD[r0][6], sD[r0][7], sD[r1][6], sD[r1][7], cA4.w, cH4.w, cV4.w, cD4.w);
        }

        const int S = 32;
        float* base = out + OFF3 + (size_t)img * 4ull * S * S;
        const int gi = ty * 4 + qi, gj = tx * 4;
        const size_t o = (size_t)gi * S + gj;
        *reinterpret_cast<float4*>(base + o)                 = cA4;
        *reinterpret_cast<float4*>(base + (size_t)S * S + o) = cH4;
        *reinterpret_cast<float4*>(base + 2ull * S * S + o)  = cV4;
        *reinterpret_cast<float4*>(base + 3ull * S * S + o)  = cD4;
    }
}

extern "C" void kernel_launch(void* const* d_in, const int* in_sizes, int n_in,
                              void* d_out, int out_size) {
    const float* x = (const float*)d_in[0];
    float* out     = (float*)d_out;
    dim3 grid(8, 8, NIMG);
    fwt_kernel<<<grid, 256>>>(x, out);
}

// round 14
// speedup vs baseline: 1.1984x; 1.0035x over previous
#include <cuda_runtime.h>

// FINAL: 4-level 2D Haar DWT, fully fused, register-level level-0 (R2 config,
// best measured: 72.2us wall / 66.3us ncu, DRAM=79%, 6.26 TB/s).
// Converged: tile-shape (64x64/128x64/64x128), cache hints (ld/st .CS combos),
// persistent grid, tail widths, and lane remaps all measured neutral-or-worse.
// Kernel is at the practical mixed-stream HBM ceiling (~78% of 8TB/s spec).
//
// Input : x (64, 3, 512, 512) f32 -> 192 images of 512x512
// Output: concat of levels l=0..3, each (192, 4, S, S), S = 256 >> l
//   subband order: 0=cA, 1=cH, 2=cV, 3=cD
// Block = 256 threads, tile = 64x64 input. Grid: (8, 8, 192).

#define NIMG 192
#define HW   512

#define OFF0 0ull
#define OFF1 (OFF0 + (unsigned long long)NIMG * 4ull * 256ull * 256ull)
#define OFF2 (OFF1 + (unsigned long long)NIMG * 4ull * 128ull * 128ull)
#define OFF3 (OFF2 + (unsigned long long)NIMG * 4ull *  64ull *  64ull)

#define HAAR(a, b, c, d, cA, cH, cV, cD)                    \
    do {                                                    \
        float _hs0 = (a) + (b), _hd0 = (a) - (b);           \
        float _hs1 = (c) + (d), _hd1 = (c) - (d);           \
        (cA) = (_hs0 + _hs1) * 0.5f;                        \
        (cH) = (_hs0 - _hs1) * 0.5f;                        \
        (cV) = (_hd0 + _hd1) * 0.5f;                        \
        (cD) = (_hd0 - _hd1) * 0.5f;                        \
    } while (0)

__global__ __launch_bounds__(256) void fwt_kernel(const float* __restrict__ x,
                                                  float* __restrict__ out) {
    const int img = blockIdx.z;
    const int ty  = blockIdx.y;
    const int tx  = blockIdx.x;
    const int tid = threadIdx.x;

    __shared__ float sB[32][33];  // level-0 cA
    __shared__ float sC[16][17];  // level-1 cA
    __shared__ float sD[8][9];    // level-2 cA

    // ---- level 0: direct global -> registers -> global, S=256 ----
    {
        const int qi  = tid >> 3;   // 0..31 quad row
        const int qjg = tid & 7;    // group of 4 quads -> input cols qjg*8..+7

        const float* src = x + ((size_t)img * HW + (size_t)ty * 64 + 2 * qi) * HW
                             + (size_t)tx * 64 + qjg * 8;
        const float4 r0a = *reinterpret_cast<const float4*>(src);
        const float4 r0b = *reinterpret_cast<const float4*>(src + 4);
        const float4 r1a = *reinterpret_cast<const float4*>(src + HW);
        const float4 r1b = *reinterpret_cast<const float4*>(src + HW + 4);

        float4 cA4, cH4, cV4, cD4;
        HAAR(r0a.x, r0a.y, r1a.x, r1a.y, cA4.x, cH4.x, cV4.x, cD4.x);
        HAAR(r0a.z, r0a.w, r1a.z, r1a.w, cA4.y, cH4.y, cV4.y, cD4.y);
        HAAR(r0b.x, r0b.y, r1b.x, r1b.y, cA4.z, cH4.z, cV4.z, cD4.z);
        HAAR(r0b.z, r0b.w, r1b.z, r1b.w, cA4.w, cH4.w, cV4.w, cD4.w);

        const int S = 256;
        float* base = out + OFF0 + (size_t)img * 4ull * S * S;
        const int gi = ty * 32 + qi, gj = tx * 32 + qjg * 4;
        const size_t o = (size_t)gi * S + gj;
        *reinterpret_cast<float4*>(base + o)                 = cA4;
        *reinterpret_cast<float4*>(base + (size_t)S * S + o) = cH4;
        *reinterpret_cast<float4*>(base + 2ull * S * S + o)  = cV4;
        *reinterpret_cast<float4*>(base + 3ull * S * S + o)  = cD4;

        sB[qi][qjg * 4 + 0] = cA4.x;
        sB[qi][qjg * 4 + 1] = cA4.y;
        sB[qi][qjg * 4 + 2] = cA4.z;
        sB[qi][qjg * 4 + 3] = cA4.w;
    }
    __syncthreads();

    // ---- level 1: 32x32 -> 16x16, S=128 (64 threads x 4 quads) ----
    if (tid < 64) {
        const int qi  = tid >> 2;   // 0..15
        const int qjg = tid & 3;    // cols qjg*8..+7 of sB

        float4 cA4, cH4, cV4, cD4;
        {
            const int r0 = 2 * qi, r1 = 2 * qi + 1, c0 = qjg * 8;
            HAAR(sB[r0][c0 + 0], sB[r0][c0 + 1], sB[r1][c0 + 0], sB[r1][c0 + 1],
                 cA4.x, cH4.x, cV4.x, cD4.x);
            HAAR(sB[r0][c0 + 2], sB[r0][c0 + 3], sB[r1][c0 + 2], sB[r1][c0 + 3],
                 cA4.y, cH4.y, cV4.y, cD4.y);
            HAAR(sB[r0][c0 + 4], sB[r0][c0 + 5], sB[r1][c0 + 4], sB[r1][c0 + 5],
                 cA4.z, cH4.z, cV4.z, cD4.z);
            HAAR(sB[r0][c0 + 6], sB[r0][c0 + 7], sB[r1][c0 + 6], sB[r1][c0 + 7],
                 cA4.w, cH4.w, cV4.w, cD4.w);
        }

        const int S = 128;
        float* base = out + OFF1 + (size_t)img * 4ull * S * S;
        const int gi = ty * 16 + qi, gj = tx * 16 + qjg * 4;
        const size_t o = (size_t)gi * S + gj;
        *reinterpret_cast<float4*>(base + o)                 = cA4;
        *reinterpret_cast<float4*>(base + (size_t)S * S + o) = cH4;
        *reinterpret_cast<float4*>(base + 2ull * S * S + o)  = cV4;
        *reinterpret_cast<float4*>(base + 3ull * S * S + o)  = cD4;

        sC[qi][qjg * 4 + 0] = cA4.x;
        sC[qi][qjg * 4 + 1] = cA4.y;
        sC[qi][qjg * 4 + 2] = cA4.z;
        sC[qi][qjg * 4 + 3] = cA4.w;
    }
    __syncthreads();

    // ---- level 2: 16x16 -> 8x8, S=64 (16 threads x 4 quads) ----
    if (tid < 16) {
        const int qi  = tid >> 1;   // 0..7
        const int qjg = tid & 1;    // cols qjg*8..+7 of sC

        float4 cA4, cH4, cV4, cD4;
        {
            const int r0 = 2 * qi, r1 = 2 * qi + 1, c0 = qjg * 8;
            HAAR(sC[r0][c0 + 0], sC[r0][c0 + 1], sC[r1][c0 + 0], sC[r1][c0 + 1],
                 cA4.x, cH4.x, cV4.x, cD4.x);
            HAAR(sC[r0][c0 + 2], sC[r0][c0 + 3], sC[r1][c0 + 2], sC[r1][c0 + 3],
                 cA4.y, cH4.y, cV4.y, cD4.y);
            HAAR(sC[r0][c0 + 4], sC[r0][c0 + 5], sC[r1][c0 + 4], sC[r1][c0 + 5],
                 cA4.z, cH4.z, cV4.z, cD4.z);
            HAAR(sC[r0][c0 + 6], sC[r0][c0 + 7], sC[r1][c0 + 6], sC[r1][c0 + 7],
                 cA4.w, cH4.w, cV4.w, cD4.w);
        }

        const int S = 64;
        float* base = out + OFF2 + (size_t)img * 4ull * S * S;
        const int gi = ty * 8 + qi, gj = tx * 8 + qjg * 4;
        const size_t o = (size_t)gi * S + gj;
        *reinterpret_cast<float4*>(base + o)                 = cA4;
        *reinterpret_cast<float4*>(base + (size_t)S * S + o) = cH4;
        *reinterpret_cast<float4*>(base + 2ull * S * S + o)  = cV4;
        *reinterpret_cast<float4*>(base + 3ull * S * S + o)  = cD4;

        sD[qi][qjg * 4 + 0] = cA4.x;
        sD[qi][qjg * 4 + 1] = cA4.y;
        sD[qi][qjg * 4 + 2] = cA4.z;
        sD[qi][qjg * 4 + 3] = cA4.w;
    }
    __syncthreads();

    // ---- level 3: 8x8 -> 4x4, S=32 (4 threads x 4 quads) ----
    if (tid < 4) {
        const int qi = tid;  // 0..3, full 4-quad row

        float4 cA4, cH4, cV4, cD4;
        {
            const int r0 = 2 * qi, r1 = 2 * qi + 1;
            HAAR(sD[r0][0], sD[r0][1], sD[r1][0], sD[r1][1], cA4.x, cH4.x, cV4.x, cD4.x);
            HAAR(sD[r0][2], sD[r0][3], sD[r1][2], sD[r1][3], cA4.y, cH4.y, cV4.y, cD4.y);
            HAAR(sD[r0][4], sD[r0][5], sD[r1][4], sD[r1][5], cA4.z, cH4.z, cV4.z, cD4.z);
            HAAR(sD[r0][6], sD[r0][7], sD[r1][6], sD[r1][7], cA4.w, cH4.w, cV4.w, cD4.w);
        }

        const int S = 32;
        float* base = out + OFF3 + (size_t)img * 4ull * S * S;
        const int gi = ty * 4 + qi, gj = tx * 4;
        const size_t o = (size_t)gi * S + gj;
        *reinterpret_cast<float4*>(base + o)                 = cA4;
        *reinterpret_cast<float4*>(base + (size_t)S * S + o) = cH4;
        *reinterpret_cast<float4*>(base + 2ull * S * S + o)  = cV4;
        *reinterpret_cast<float4*>(base + 3ull * S * S + o)  = cD4;
    }
}

extern "C" void kernel_launch(void* const* d_in, const int* in_sizes, int n_in,
                              void* d_out, int out_size) {
    const float* x = (const float*)d_in[0];
    float* out     = (float*)d_out;
    dim3 grid(8, 8, NIMG);
    fwt_kernel<<<grid, 256>>>(x, out);
}

// round 15
// speedup vs baseline: 1.2042x; 1.0048x over previous
#include <cuda_runtime.h>

// FINAL (converged): 4-level 2D Haar DWT, fully fused, register-level level-0.
// Best measured config: 72.2-73.5us wall / 66.3-67.4us ncu across repeats,
// DRAM=77.5-79.0%, ~6.2 TB/s. Exploration summary:
//   - tile shapes 64x64 / 128x64 / 64x128: 64x64 best (wide tile broke
//     per-instruction sector utilization, -24%)
//   - cache hints (.cs loads, .cs stores, both): all regressions
//   - persistent 1-wave grid: -16% (block tails land on critical path)
//   - tail widths and lane remaps: neutral
// Kernel sits at the practical mixed read+write HBM ceiling (~78% of spec);
// no compute pipe above 11%, occ 91%.
//
// Input : x (64, 3, 512, 512) f32 -> 192 images of 512x512
// Output: concat of levels l=0..3, each (192, 4, S, S), S = 256 >> l
//   subband order: 0=cA, 1=cH, 2=cV, 3=cD
// Block = 256 threads, tile = 64x64 input. Grid: (8, 8, 192).

#define NIMG 192
#define HW   512

#define OFF0 0ull
#define OFF1 (OFF0 + (unsigned long long)NIMG * 4ull * 256ull * 256ull)
#define OFF2 (OFF1 + (unsigned long long)NIMG * 4ull * 128ull * 128ull)
#define OFF3 (OFF2 + (unsigned long long)NIMG * 4ull *  64ull *  64ull)

#define HAAR(a, b, c, d, cA, cH, cV, cD)                    \
    do {                                                    \
        float _hs0 = (a) + (b), _hd0 = (a) - (b);           \
        float _hs1 = (c) + (d), _hd1 = (c) - (d);           \
        (cA) = (_hs0 + _hs1) * 0.5f;                        \
        (cH) = (_hs0 - _hs1) * 0.5f;                        \
        (cV) = (_hd0 + _hd1) * 0.5f;                        \
        (cD) = (_hd0 - _hd1) * 0.5f;                        \
    } while (0)

__global__ __launch_bounds__(256) void fwt_kernel(const float* __restrict__ x,
                                                  float* __restrict__ out) {
    const int img = blockIdx.z;
    const int ty  = blockIdx.y;
    const int tx  = blockIdx.x;
    const int tid = threadIdx.x;

    __shared__ float sB[32][33];  // level-0 cA
    __shared__ float sC[16][17];  // level-1 cA
    __shared__ float sD[8][9];    // level-2 cA

    // ---- level 0: direct global -> registers -> global, S=256 ----
    {
        const int qi  = tid >> 3;   // 0..31 quad row
        const int qjg = tid & 7;    // group of 4 quads -> input cols qjg*8..+7

        const float* src = x + ((size_t)img * HW + (size_t)ty * 64 + 2 * qi) * HW
                             + (size_t)tx * 64 + qjg * 8;
        const float4 r0a = *reinterpret_cast<const float4*>(src);
        const float4 r0b = *reinterpret_cast<const float4*>(src + 4);
        const float4 r1a = *reinterpret_cast<const float4*>(src + HW);
        const float4 r1b = *reinterpret_cast<const float4*>(src + HW + 4);

        float4 cA4, cH4, cV4, cD4;
        HAAR(r0a.x, r0a.y, r1a.x, r1a.y, cA4.x, cH4.x, cV4.x, cD4.x);
        HAAR(r0a.z, r0a.w, r1a.z, r1a.w, cA4.y, cH4.y, cV4.y, cD4.y);
        HAAR(r0b.x, r0b.y, r1b.x, r1b.y, cA4.z, cH4.z, cV4.z, cD4.z);
        HAAR(r0b.z, r0b.w, r1b.z, r1b.w, cA4.w, cH4.w, cV4.w, cD4.w);

        const int S = 256;
        float* base = out + OFF0 + (size_t)img * 4ull * S * S;
        const int gi = ty * 32 + qi, gj = tx * 32 + qjg * 4;
        const size_t o = (size_t)gi * S + gj;
        *reinterpret_cast<float4*>(base + o)                 = cA4;
        *reinterpret_cast<float4*>(base + (size_t)S * S + o) = cH4;
        *reinterpret_cast<float4*>(base + 2ull * S * S + o)  = cV4;
        *reinterpret_cast<float4*>(base + 3ull * S * S + o)  = cD4;

        sB[qi][qjg * 4 + 0] = cA4.x;
        sB[qi][qjg * 4 + 1] = cA4.y;
        sB[qi][qjg * 4 + 2] = cA4.z;
        sB[qi][qjg * 4 + 3] = cA4.w;
    }
    __syncthreads();

    // ---- level 1: 32x32 -> 16x16, S=128 (64 threads x 4 quads) ----
    if (tid < 64) {
        const int qi  = tid >> 2;   // 0..15
        const int qjg = tid & 3;    // cols qjg*8..+7 of sB

        float4 cA4, cH4, cV4, cD4;
        {
            const int r0 = 2 * qi, r1 = 2 * qi + 1, c0 = qjg * 8;
            HAAR(sB[r0][c0 + 0], sB[r0][c0 + 1], sB[r1][c0 + 0], sB[r1][c0 + 1],
                 cA4.x, cH4.x, cV4.x, cD4.x);
            HAAR(sB[r0][c0 + 2], sB[r0][c0 + 3], sB[r1][c0 + 2], sB[r1][c0 + 3],
                 cA4.y, cH4.y, cV4.y, cD4.y);
            HAAR(sB[r0][c0 + 4], sB[r0][c0 + 5], sB[r1][c0 + 4], sB[r1][c0 + 5],
                 cA4.z, cH4.z, cV4.z, cD4.z);
            HAAR(sB[r0][c0 + 6], sB[r0][c0 + 7], sB[r1][c0 + 6], sB[r1][c0 + 7],
                 cA4.w, cH4.w, cV4.w, cD4.w);
        }

        const int S = 128;
        float* base = out + OFF1 + (size_t)img * 4ull * S * S;
        const int gi = ty * 16 + qi, gj = tx * 16 + qjg * 4;
        const size_t o = (size_t)gi * S + gj;
        *reinterpret_cast<float4*>(base + o)                 = cA4;
        *reinterpret_cast<float4*>(base + (size_t)S * S + o) = cH4;
        *reinterpret_cast<float4*>(base + 2ull * S * S + o)  = cV4;
        *reinterpret_cast<float4*>(base + 3ull * S * S + o)  = cD4;

        sC[qi][qjg * 4 + 0] = cA4.x;
        sC[qi][qjg * 4 + 1] = cA4.y;
        sC[qi][qjg * 4 + 2] = cA4.z;
        sC[qi][qjg * 4 + 3] = cA4.w;
    }
    __syncthreads();

    // ---- level 2: 16x16 -> 8x8, S=64 (16 threads x 4 quads) ----
    if (tid < 16) {
        const int qi  = tid >> 1;   // 0..7
        const int qjg = tid & 1;    // cols qjg*8..+7 of sC

        float4 cA4, cH4, cV4, cD4;
        {
            const int r0 = 2 * qi, r1 = 2 * qi + 1, c0 = qjg * 8;
            HAAR(sC[r0][c0 + 0], sC[r0][c0 + 1], sC[r1][c0 + 0], sC[r1][c0 + 1],
                 cA4.x, cH4.x, cV4.x, cD4.x);
            HAAR(sC[r0][c0 + 2], sC[r0][c0 + 3], sC[r1][c0 + 2], sC[r1][c0 + 3],
                 cA4.y, cH4.y, cV4.y, cD4.y);
            HAAR(sC[r0][c0 + 4], sC[r0][c0 + 5], sC[r1][c0 + 4], sC[r1][c0 + 5],
                 cA4.z, cH4.z, cV4.z, cD4.z);
            HAAR(sC[r0][c0 + 6], sC[r0][c0 + 7], sC[r1][c0 + 6], sC[r1][c0 + 7],
                 cA4.w, cH4.w, cV4.w, cD4.w);
        }

        const int S = 64;
        float* base = out + OFF2 + (size_t)img * 4ull * S * S;
        const int gi = ty * 8 + qi, gj = tx * 8 + qjg * 4;
        const size_t o = (size_t)gi * S + gj;
        *reinterpret_cast<float4*>(base + o)                 = cA4;
        *reinterpret_cast<float4*>(base + (size_t)S * S + o) = cH4;
        *reinterpret_cast<float4*>(base + 2ull * S * S + o)  = cV4;
        *reinterpret_cast<float4*>(base + 3ull * S * S + o)  = cD4;

        sD[qi][qjg * 4 + 0] = cA4.x;
        sD[qi][qjg * 4 + 1] = cA4.y;
        sD[qi][qjg * 4 + 2] = cA4.z;
        sD[qi][qjg * 4 + 3] = cA4.w;
    }
    __syncthreads();

    // ---- level 3: 8x8 -> 4x4, S=32 (4 threads x 4 quads) ----
    if (tid < 4) {
        const int qi = tid;  // 0..3, full 4-quad row

        float4 cA4, cH4, cV4, cD4;
        {
            const int r0 = 2 * qi, r1 = 2 * qi + 1;
            HAAR(sD[r0][0], sD[r0][1], sD[r1][0], sD[r1][1], cA4.x, cH4.x, cV4.x, cD4.x);
            HAAR(sD[r0][2], sD[r0][3], sD[r1][2], sD[r1][3], cA4.y, cH4.y, cV4.y, cD4.y);
            HAAR(sD[r0][4], sD[r0][5], sD[r1][4], sD[r1][5], cA4.z, cH4.z, cV4.z, cD4.z);
            HAAR(sD[r0][6], sD[r0][7], sD[r1][6], sD[r1][7], cA4.w, cH4.w, cV4.w, cD4.w);
        }

        const int S = 32;
        float* base = out + OFF3 + (size_t)img * 4ull * S * S;
        const int gi = ty * 4 + qi, gj = tx * 4;
        const size_t o = (size_t)gi * S + gj;
        *reinterpret_cast<float4*>(base + o)                 = cA4;
        *reinterpret_cast<float4*>(base + (size_t)S * S + o) = cH4;
        *reinterpret_cast<float4*>(base + 2ull * S * S + o)  = cV4;
        *reinterpret_cast<float4*>(base + 3ull * S * S + o)  = cD4;
    }
}

extern "C" void kernel_launch(void* const* d_in, const int* in_sizes, int n_in,
                              void* d_out, int out_size) {
    const float* x = (const float*)d_in[0];
    float* out     = (float*)d_out;
    dim3 grid(8, 8, NIMG);
    fwt_kernel<<<grid, 256>>>(x, out);
}